// round 3
// baseline (speedup 1.0000x reference)
#include <cuda_runtime.h>
#include <math.h>

#define BATCH  64
#define NLEN   1500
#define NFREQ  1251
#define FCHUNK 64
#define NCHUNKS ((NFREQ + FCHUNK - 1) / FCHUNK)   // 20

__device__ float g_psd[BATCH * NFREQ];
__device__ float g_per[BATCH];

// ---- packed f32x2 helpers (sm_103a) ----
__device__ __forceinline__ unsigned long long pk2(float lo, float hi) {
    unsigned long long r;
    asm("mov.b64 %0, {%1, %2};" : "=l"(r) : "f"(lo), "f"(hi));
    return r;
}
__device__ __forceinline__ void upk2(unsigned long long v, float& lo, float& hi) {
    asm("mov.b64 {%0, %1}, %2;" : "=f"(lo), "=f"(hi) : "l"(v));
}
__device__ __forceinline__ unsigned long long fma2(unsigned long long a,
                                                   unsigned long long b,
                                                   unsigned long long c) {
    unsigned long long d;
    asm("fma.rn.f32x2 %0, %1, %2, %3;" : "=l"(d) : "l"(a), "l"(b), "l"(c));
    return d;
}

// Frequency grid value, matching jnp.arange semantics: iota*step + start in f32
__device__ __forceinline__ float grid_f(int i) {
    return __fadd_rn(__fmul_rn((float)i, 0.002f), 0.5f);
}

// ============================================================================
// Kernel 1: Goertzel PSD. One block = (batch pair, 64-frequency chunk).
// Each thread runs two interleaved Goertzel recurrences (one per batch of the
// pair) packed into f32x2 registers. 2 packed FMAs + 1 broadcast LDS.64 / step.
// ============================================================================
__global__ void __launch_bounds__(FCHUNK)
goertzel_kernel(const float* __restrict__ x, const float* __restrict__ fs)
{
    __shared__ unsigned long long sx[NLEN];

    const int bp = blockIdx.y;           // batch pair 0..31
    const int b0 = 2 * bp;
    const int b1 = 2 * bp + 1;
    const float* __restrict__ x0 = x + b0 * NLEN;
    const float* __restrict__ x1 = x + b1 * NLEN;

    for (int i = threadIdx.x; i < NLEN; i += FCHUNK)
        sx[i] = pk2(x0[i], x1[i]);
    __syncthreads();

    const int f  = blockIdx.x * FCHUNK + threadIdx.x;
    const int fc = (f < NFREQ) ? f : (NFREQ - 1);   // clamp: keep loop uniform
    const float fval = grid_f(fc);

    const float TWO_PI = 6.283185307179586476925f;
    const float th0 = TWO_PI * fval / fs[b0];
    const float th1 = TWO_PI * fval / fs[b1];
    float c0, sn0, c1, sn1;
    sincosf(th0, &sn0, &c0);
    sincosf(th1, &sn1, &c1);

    const unsigned long long coeff = pk2(2.0f * c0, 2.0f * c1);
    const unsigned long long NEG1  = pk2(-1.0f, -1.0f);
    unsigned long long s1 = 0ull;   // (0.0f, 0.0f)
    unsigned long long s2 = 0ull;

    #pragma unroll 4
    for (int n = 0; n < NLEN; n++) {
        const unsigned long long xv = sx[n];
        const unsigned long long t  = fma2(s2, NEG1, xv);     // x - s2
        const unsigned long long sn = fma2(coeff, s1, t);     // 2c*s1 + (x - s2)
        s2 = s1;
        s1 = sn;
    }

    float a0, a1, d0, d1;
    upk2(s1, a0, a1);
    upk2(s2, d0, d1);

    // |X|^2 = s1^2 + s2^2 - 2c*s1*s2 = (s1 - c*s2)^2 + (sin*s2)^2  (stable form)
    float u0 = a0 - c0 * d0;
    float v0 = sn0 * d0;
    float p0 = u0 * u0 + v0 * v0;
    float u1 = a1 - c1 * d1;
    float v1 = sn1 * d1;
    float p1 = u1 * u1 + v1 * v1;

    if (f < NFREQ) {
        g_psd[b0 * NFREQ + f] = p0;
        g_psd[b1 * NFREQ + f] = p1;
    }
}

// ============================================================================
// Kernel 2: per-batch log-softmax at the argmin-|f - f_true| index.
// One block per batch, 128 threads: pass1 max, pass2 sumexp + argmin.
// ============================================================================
__global__ void __launch_bounds__(128)
reduce_kernel(const float* __restrict__ f_true)
{
    const int b   = blockIdx.x;
    const int tid = threadIdx.x;
    const float* __restrict__ psd = g_psd + b * NFREQ;

    __shared__ float smax[4];
    __shared__ float ssum[4];
    __shared__ float sbd[4];
    __shared__ int   sbi[4];

    // ---- pass 1: max ----
    float m = -1e30f;
    for (int f = tid; f < NFREQ; f += 128)
        m = fmaxf(m, psd[f]);
    #pragma unroll
    for (int o = 16; o > 0; o >>= 1)
        m = fmaxf(m, __shfl_down_sync(0xffffffffu, m, o));
    if ((tid & 31) == 0) smax[tid >> 5] = m;
    __syncthreads();
    m = fmaxf(fmaxf(smax[0], smax[1]), fmaxf(smax[2], smax[3]));

    // ---- pass 2: sum(exp(psd-m)) + argmin |grid - f_true| (first occurrence) ----
    const float ft = f_true[b];
    float se = 0.0f;
    float bd = 1e30f;
    int   bi = NFREQ;
    for (int f = tid; f < NFREQ; f += 128) {
        se += expf(psd[f] - m);
        const float d = fabsf(grid_f(f) - ft);
        if (d < bd) { bd = d; bi = f; }   // strictly <: keeps smallest f per lane
    }
    #pragma unroll
    for (int o = 16; o > 0; o >>= 1) {
        se += __shfl_down_sync(0xffffffffu, se, o);
        const float od = __shfl_down_sync(0xffffffffu, bd, o);
        const int   oi = __shfl_down_sync(0xffffffffu, bi, o);
        if (od < bd || (od == bd && oi < bi)) { bd = od; bi = oi; }
    }
    if ((tid & 31) == 0) {
        const int w = tid >> 5;
        ssum[w] = se; sbd[w] = bd; sbi[w] = bi;
    }
    __syncthreads();

    if (tid == 0) {
        float tot = 0.0f, fbd = 1e30f;
        int   fbi = NFREQ;
        #pragma unroll
        for (int w = 0; w < 4; w++) {
            tot += ssum[w];
            if (sbd[w] < fbd || (sbd[w] == fbd && sbi[w] < fbi)) {
                fbd = sbd[w]; fbi = sbi[w];
            }
        }
        const float p = expf(psd[fbi] - m) / tot;   // softmax[idx]
        g_per[b] = -logf(p + 1e-8f);
    }
}

// ============================================================================
// Kernel 3: mean over batch -> scalar output
// ============================================================================
__global__ void __launch_bounds__(64)
mean_kernel(float* __restrict__ out)
{
    const int tid = threadIdx.x;
    float v = g_per[tid];
    #pragma unroll
    for (int o = 16; o > 0; o >>= 1)
        v += __shfl_down_sync(0xffffffffu, v, o);
    __shared__ float sw[2];
    if ((tid & 31) == 0) sw[tid >> 5] = v;
    __syncthreads();
    if (tid == 0)
        out[0] = (sw[0] + sw[1]) * (1.0f / (float)BATCH);
}

// ============================================================================
extern "C" void kernel_launch(void* const* d_in, const int* in_sizes, int n_in,
                              void* d_out, int out_size)
{
    const float* x      = (const float*)d_in[0];   // [64, 1500]
    const float* f_true = (const float*)d_in[1];   // [64]
    const float* fs     = (const float*)d_in[2];   // [64]
    float* out = (float*)d_out;                    // scalar

    dim3 g1(NCHUNKS, BATCH / 2);                   // (20, 32)
    goertzel_kernel<<<g1, FCHUNK>>>(x, fs);
    reduce_kernel<<<BATCH, 128>>>(f_true);
    mean_kernel<<<1, 64>>>(out);
}

// round 4
// speedup vs baseline: 1.0234x; 1.0234x over previous
#include <cuda_runtime.h>
#include <math.h>

#define BATCH  64
#define NLEN   1500
#define NFREQ  1251
#define FCHUNK 64
#define NCHUNKS ((NFREQ + FCHUNK - 1) / FCHUNK)   // 20

__device__ float g_psd[BATCH * NFREQ];
__device__ float g_per[BATCH];

// ---- packed f32x2 helpers (sm_103a) ----
__device__ __forceinline__ unsigned long long pk2(float lo, float hi) {
    unsigned long long r;
    asm("mov.b64 %0, {%1, %2};" : "=l"(r) : "f"(lo), "f"(hi));
    return r;
}
__device__ __forceinline__ void upk2(unsigned long long v, float& lo, float& hi) {
    asm("mov.b64 {%0, %1}, %2;" : "=f"(lo), "=f"(hi) : "l"(v));
}
__device__ __forceinline__ unsigned long long fma2(unsigned long long a,
                                                   unsigned long long b,
                                                   unsigned long long c) {
    unsigned long long d;
    asm("fma.rn.f32x2 %0, %1, %2, %3;" : "=l"(d) : "l"(a), "l"(b), "l"(c));
    return d;
}

// Frequency grid value, matching jnp.arange semantics: iota*step + start in f32
__device__ __forceinline__ float grid_f(int i) {
    return __fadd_rn(__fmul_rn((float)i, 0.002f), 0.5f);
}

// ============================================================================
// Kernel 1: Goertzel PSD. One block = (batch pair, 64-frequency chunk).
// Each thread runs two interleaved Goertzel recurrences (one per batch of the
// pair) packed into f32x2 registers. 2 packed FMAs + 1 broadcast LDS.64 / step.
// ============================================================================
__global__ void __launch_bounds__(FCHUNK)
goertzel_kernel(const float* __restrict__ x, const float* __restrict__ fs)
{
    __shared__ unsigned long long sx[NLEN];

    const int bp = blockIdx.y;           // batch pair 0..31
    const int b0 = 2 * bp;
    const int b1 = 2 * bp + 1;
    const float* __restrict__ x0 = x + b0 * NLEN;
    const float* __restrict__ x1 = x + b1 * NLEN;

    for (int i = threadIdx.x; i < NLEN; i += FCHUNK)
        sx[i] = pk2(x0[i], x1[i]);
    __syncthreads();

    const int f  = blockIdx.x * FCHUNK + threadIdx.x;
    const int fc = (f < NFREQ) ? f : (NFREQ - 1);   // clamp: keep loop uniform
    const float fval = grid_f(fc);

    const float TWO_PI = 6.283185307179586476925f;
    const float th0 = TWO_PI * fval / fs[b0];
    const float th1 = TWO_PI * fval / fs[b1];
    float c0, sn0, c1, sn1;
    sincosf(th0, &sn0, &c0);
    sincosf(th1, &sn1, &c1);

    const unsigned long long coeff = pk2(2.0f * c0, 2.0f * c1);
    const unsigned long long NEG1  = pk2(-1.0f, -1.0f);
    unsigned long long s1 = 0ull;   // (0.0f, 0.0f)
    unsigned long long s2 = 0ull;

    #pragma unroll 4
    for (int n = 0; n < NLEN; n++) {
        const unsigned long long xv = sx[n];
        const unsigned long long t  = fma2(s2, NEG1, xv);     // x - s2
        const unsigned long long sn = fma2(coeff, s1, t);     // 2c*s1 + (x - s2)
        s2 = s1;
        s1 = sn;
    }

    float a0, a1, d0, d1;
    upk2(s1, a0, a1);
    upk2(s2, d0, d1);

    // |X|^2 = s1^2 + s2^2 - 2c*s1*s2 = (s1 - c*s2)^2 + (sin*s2)^2  (stable form)
    float u0 = a0 - c0 * d0;
    float v0 = sn0 * d0;
    float p0 = u0 * u0 + v0 * v0;
    float u1 = a1 - c1 * d1;
    float v1 = sn1 * d1;
    float p1 = u1 * u1 + v1 * v1;

    if (f < NFREQ) {
        g_psd[b0 * NFREQ + f] = p0;
        g_psd[b1 * NFREQ + f] = p1;
    }
}

// ============================================================================
// Kernel 2: per-batch log-softmax at the argmin-|f - f_true| index.
// One block per batch, 128 threads: pass1 max, pass2 sumexp + argmin.
// ============================================================================
__global__ void __launch_bounds__(128)
reduce_kernel(const float* __restrict__ f_true)
{
    const int b   = blockIdx.x;
    const int tid = threadIdx.x;
    const float* __restrict__ psd = g_psd + b * NFREQ;

    __shared__ float smax[4];
    __shared__ float ssum[4];
    __shared__ float sbd[4];
    __shared__ int   sbi[4];

    // ---- pass 1: max ----
    float m = -1e30f;
    for (int f = tid; f < NFREQ; f += 128)
        m = fmaxf(m, psd[f]);
    #pragma unroll
    for (int o = 16; o > 0; o >>= 1)
        m = fmaxf(m, __shfl_down_sync(0xffffffffu, m, o));
    if ((tid & 31) == 0) smax[tid >> 5] = m;
    __syncthreads();
    m = fmaxf(fmaxf(smax[0], smax[1]), fmaxf(smax[2], smax[3]));

    // ---- pass 2: sum(exp(psd-m)) + argmin |grid - f_true| (first occurrence) ----
    const float ft = f_true[b];
    float se = 0.0f;
    float bd = 1e30f;
    int   bi = NFREQ;
    for (int f = tid; f < NFREQ; f += 128) {
        se += expf(psd[f] - m);
        const float d = fabsf(grid_f(f) - ft);
        if (d < bd) { bd = d; bi = f; }   // strictly <: keeps smallest f per lane
    }
    #pragma unroll
    for (int o = 16; o > 0; o >>= 1) {
        se += __shfl_down_sync(0xffffffffu, se, o);
        const float od = __shfl_down_sync(0xffffffffu, bd, o);
        const int   oi = __shfl_down_sync(0xffffffffu, bi, o);
        if (od < bd || (od == bd && oi < bi)) { bd = od; bi = oi; }
    }
    if ((tid & 31) == 0) {
        const int w = tid >> 5;
        ssum[w] = se; sbd[w] = bd; sbi[w] = bi;
    }
    __syncthreads();

    if (tid == 0) {
        float tot = 0.0f, fbd = 1e30f;
        int   fbi = NFREQ;
        #pragma unroll
        for (int w = 0; w < 4; w++) {
            tot += ssum[w];
            if (sbd[w] < fbd || (sbd[w] == fbd && sbi[w] < fbi)) {
                fbd = sbd[w]; fbi = sbi[w];
            }
        }
        const float p = expf(psd[fbi] - m) / tot;   // softmax[idx]
        g_per[b] = -logf(p + 1e-8f);
    }
}

// ============================================================================
// Kernel 3: mean over batch -> scalar output
// ============================================================================
__global__ void __launch_bounds__(64)
mean_kernel(float* __restrict__ out)
{
    const int tid = threadIdx.x;
    float v = g_per[tid];
    #pragma unroll
    for (int o = 16; o > 0; o >>= 1)
        v += __shfl_down_sync(0xffffffffu, v, o);
    __shared__ float sw[2];
    if ((tid & 31) == 0) sw[tid >> 5] = v;
    __syncthreads();
    if (tid == 0)
        out[0] = (sw[0] + sw[1]) * (1.0f / (float)BATCH);
}

// ============================================================================
extern "C" void kernel_launch(void* const* d_in, const int* in_sizes, int n_in,
                              void* d_out, int out_size)
{
    const float* x      = (const float*)d_in[0];   // [64, 1500]
    const float* f_true = (const float*)d_in[1];   // [64]
    const float* fs     = (const float*)d_in[2];   // [64]
    float* out = (float*)d_out;                    // scalar

    dim3 g1(NCHUNKS, BATCH / 2);                   // (20, 32)
    goertzel_kernel<<<g1, FCHUNK>>>(x, fs);
    reduce_kernel<<<BATCH, 128>>>(f_true);
    mean_kernel<<<1, 64>>>(out);
}

// round 5
// speedup vs baseline: 1.1631x; 1.1365x over previous
#include <cuda_runtime.h>
#include <math.h>

#define BATCH   64
#define NLEN    1500
#define NFREQ   1251
#define FCHUNK  64
#define NCHUNKS ((NFREQ + FCHUNK - 1) / FCHUNK)   // 20
#define SEG     4
#define SEGLEN  376                                // padded: 4*376 = 1504 >= 1500
#define NPAD    (SEG * SEGLEN)                     // 1504
#define SEGU2   (SEGLEN / 2)                       // 188 ulonglong2 per segment

__device__ float g_psd[BATCH * NFREQ];
__device__ float g_per[BATCH];

// ---- packed f32x2 helpers (sm_103a) ----
__device__ __forceinline__ unsigned long long pk2(float lo, float hi) {
    unsigned long long r;
    asm("mov.b64 %0, {%1, %2};" : "=l"(r) : "f"(lo), "f"(hi));
    return r;
}
__device__ __forceinline__ void upk2(unsigned long long v, float& lo, float& hi) {
    asm("mov.b64 {%0, %1}, %2;" : "=f"(lo), "=f"(hi) : "l"(v));
}
__device__ __forceinline__ unsigned long long fma2(unsigned long long a,
                                                   unsigned long long b,
                                                   unsigned long long c) {
    unsigned long long d;
    asm("fma.rn.f32x2 %0, %1, %2, %3;" : "=l"(d) : "l"(a), "l"(b), "l"(c));
    return d;
}

// Frequency grid value, matching jnp.arange semantics: iota*step + start in f32
__device__ __forceinline__ float grid_f(int i) {
    return __fadd_rn(__fmul_rn((float)i, 0.002f), 0.5f);
}

// ============================================================================
// Kernel 1: segmented Goertzel PSD.
// Block = (batch pair, 64-freq chunk), 256 threads = 64 freq lanes x 4 time
// segments. Each thread: 376-step Goertzel over its segment, two batches
// packed in f32x2. Segment partials are complex-rotated and reduced in SMEM.
// ============================================================================
__global__ void __launch_bounds__(256)
goertzel_kernel(const float* __restrict__ x, const float* __restrict__ fs)
{
    __shared__ ulonglong2 sx2[NPAD / 2];       // 752 * 16B = 12032 B
    __shared__ float4     red[FCHUNK * (SEG - 1)];

    const int tid = threadIdx.x;
    const int bp  = blockIdx.y;                // batch pair 0..31
    const int b0  = 2 * bp;
    const int b1  = 2 * bp + 1;

    // ---- load & pack x: 2 samples per ulonglong2 entry ----
    const float2* __restrict__ x0v = (const float2*)(x + b0 * NLEN);
    const float2* __restrict__ x1v = (const float2*)(x + b1 * NLEN);
    for (int i = tid; i < NLEN / 2; i += 256) {
        const float2 a = x0v[i];
        const float2 b = x1v[i];
        ulonglong2 v;
        v.x = pk2(a.x, b.x);
        v.y = pk2(a.y, b.y);
        sx2[i] = v;
    }
    if (tid < (NPAD - NLEN) / 2) {             // zero-pad entries 750,751
        ulonglong2 z; z.x = 0ull; z.y = 0ull;
        sx2[NLEN / 2 + tid] = z;
    }
    __syncthreads();

    const int fl  = tid & (FCHUNK - 1);        // frequency lane 0..63
    const int seg = tid >> 6;                  // time segment 0..3
    const int f   = blockIdx.x * FCHUNK + fl;
    const int fc  = (f < NFREQ) ? f : (NFREQ - 1);
    const float fval = grid_f(fc);

    const float TWO_PI = 6.283185307179586476925f;
    const float w0 = TWO_PI * fval / fs[b0];
    const float w1 = TWO_PI * fval / fs[b1];
    float c0, sn0, c1, sn1;
    sincosf(w0, &sn0, &c0);
    sincosf(w1, &sn1, &c1);

    const unsigned long long coeff = pk2(2.0f * c0, 2.0f * c1);
    const unsigned long long NEG1  = pk2(-1.0f, -1.0f);
    unsigned long long s1 = 0ull, s2 = 0ull;

    const ulonglong2* __restrict__ p = sx2 + seg * SEGU2;

    #pragma unroll 4
    for (int i = 0; i < SEGU2; i++) {
        const ulonglong2 v = p[i];
        unsigned long long t, sn;
        t  = fma2(s2, NEG1, v.x);              // x - s2
        sn = fma2(coeff, s1, t);               // 2c*s1 + (x - s2)
        s2 = s1; s1 = sn;
        t  = fma2(s2, NEG1, v.y);
        sn = fma2(coeff, s1, t);
        s2 = s1; s1 = sn;
    }

    // ---- epilogue: segment partial  P = (s1 - c*s2) + j (sin*s2),
    //      rotate by phi = -w * (n0 + SEGLEN - 1) ----
    float a0, a1, d0, d1;
    upk2(s1, a0, a1);
    upk2(s2, d0, d1);

    const float nrot = (float)(seg * SEGLEN + SEGLEN - 1);   // n0 + 375
    float rc0, rs0, rc1, rs1;
    sincosf(-w0 * nrot, &rs0, &rc0);
    sincosf(-w1 * nrot, &rs1, &rc1);

    const float gre0 = a0 - c0 * d0, gim0 = sn0 * d0;
    const float gre1 = a1 - c1 * d1, gim1 = sn1 * d1;

    float4 r;
    r.x = rc0 * gre0 - rs0 * gim0;             // batch b0: Re
    r.y = rc0 * gim0 + rs0 * gre0;             //            Im
    r.z = rc1 * gre1 - rs1 * gim1;             // batch b1: Re
    r.w = rc1 * gim1 + rs1 * gre1;             //            Im

    if (seg > 0) red[(seg - 1) * FCHUNK + fl] = r;
    __syncthreads();

    if (seg == 0 && f < NFREQ) {
        #pragma unroll
        for (int s = 0; s < SEG - 1; s++) {
            const float4 o = red[s * FCHUNK + fl];
            r.x += o.x; r.y += o.y; r.z += o.z; r.w += o.w;
        }
        g_psd[b0 * NFREQ + f] = r.x * r.x + r.y * r.y;
        g_psd[b1 * NFREQ + f] = r.z * r.z + r.w * r.w;
    }
}

// ============================================================================
// Kernel 2: per-batch single-pass online log-softmax at argmin-|f-f_true|.
// One block per batch, 256 threads.
// ============================================================================
__global__ void __launch_bounds__(256)
reduce_kernel(const float* __restrict__ f_true)
{
    const int b   = blockIdx.x;
    const int tid = threadIdx.x;
    const float* __restrict__ psd = g_psd + b * NFREQ;

    __shared__ float sm[8], ss[8], sbd[8];
    __shared__ int   sbi[8];

    const float ft = f_true[b];

    // ---- single pass: online softmax (m, s) + argmin ----
    float m  = -1e30f;
    float se = 0.0f;
    float bd = 1e30f;
    int   bi = NFREQ;
    for (int f = tid; f < NFREQ; f += 256) {
        const float v = psd[f];
        if (v > m) { se = se * expf(m - v) + 1.0f; m = v; }
        else       { se += expf(v - m); }
        const float d = fabsf(grid_f(f) - ft);
        if (d < bd) { bd = d; bi = f; }        // strict <: first occurrence/lane
    }
    #pragma unroll
    for (int o = 16; o > 0; o >>= 1) {
        const float om = __shfl_down_sync(0xffffffffu, m, o);
        const float os = __shfl_down_sync(0xffffffffu, se, o);
        const float M  = fmaxf(m, om);
        se = se * expf(m - M) + os * expf(om - M);
        m  = M;
        const float od = __shfl_down_sync(0xffffffffu, bd, o);
        const int   oi = __shfl_down_sync(0xffffffffu, bi, o);
        if (od < bd || (od == bd && oi < bi)) { bd = od; bi = oi; }
    }
    if ((tid & 31) == 0) {
        const int w = tid >> 5;
        sm[w] = m; ss[w] = se; sbd[w] = bd; sbi[w] = bi;
    }
    __syncthreads();

    if (tid == 0) {
        float M = sm[0];
        #pragma unroll
        for (int w = 1; w < 8; w++) M = fmaxf(M, sm[w]);
        float S = 0.0f, fbd = 1e30f;
        int   fbi = NFREQ;
        #pragma unroll
        for (int w = 0; w < 8; w++) {
            S += ss[w] * expf(sm[w] - M);
            if (sbd[w] < fbd || (sbd[w] == fbd && sbi[w] < fbi)) {
                fbd = sbd[w]; fbi = sbi[w];
            }
        }
        const float p = expf(psd[fbi] - M) / S;    // softmax[idx]
        g_per[b] = -logf(p + 1e-8f);
    }
}

// ============================================================================
// Kernel 3: mean over batch -> scalar output
// ============================================================================
__global__ void __launch_bounds__(64)
mean_kernel(float* __restrict__ out)
{
    const int tid = threadIdx.x;
    float v = g_per[tid];
    #pragma unroll
    for (int o = 16; o > 0; o >>= 1)
        v += __shfl_down_sync(0xffffffffu, v, o);
    __shared__ float sw[2];
    if ((tid & 31) == 0) sw[tid >> 5] = v;
    __syncthreads();
    if (tid == 0)
        out[0] = (sw[0] + sw[1]) * (1.0f / (float)BATCH);
}

// ============================================================================
extern "C" void kernel_launch(void* const* d_in, const int* in_sizes, int n_in,
                              void* d_out, int out_size)
{
    const float* x      = (const float*)d_in[0];   // [64, 1500]
    const float* f_true = (const float*)d_in[1];   // [64]
    const float* fs     = (const float*)d_in[2];   // [64]
    float* out = (float*)d_out;                    // scalar

    dim3 g1(NCHUNKS, BATCH / 2);                   // (20, 32)
    goertzel_kernel<<<g1, 256>>>(x, fs);
    reduce_kernel<<<BATCH, 256>>>(f_true);
    mean_kernel<<<1, 64>>>(out);
}